// round 3
// baseline (speedup 1.0000x reference)
#include <cuda_runtime.h>
#include <math.h>

#define EMBED 512
#define NH    8
#define DH    64
#define BATCH 2
#define SEQ   2048
#define ROWS  (BATCH*SEQ)   // 4096
#define FF    2048

// ---------------- scratch (no allocation allowed) ----------------
__device__ float g_q[ROWS*EMBED];
__device__ float g_k[ROWS*EMBED];
__device__ float g_v[ROWS*EMBED];
__device__ float g_attn[ROWS*EMBED];
__device__ float g_x[ROWS*EMBED];
__device__ float g_h[ROWS*FF];

// ---------------- GEMM: C[M,N] = A[M,K] @ B[K,N] + bias (+epilogue) ----------
#define BM 128
#define BN 128
#define BK 8
#define TM 8
#define TN 8

#define EP_BIAS 0
#define EP_RES  1
#define EP_GELU 2

__global__ __launch_bounds__(256) void sgemm_ep(
    const float* __restrict__ A, const float* __restrict__ B,
    const float* __restrict__ bias, const float* __restrict__ R,
    float* __restrict__ C, int M, int N, int K, int ep)
{
    __shared__ float As[BK][BM];
    __shared__ float Bs[BK][BN];
    const int tid = threadIdx.x;
    const int bm = blockIdx.y * BM;
    const int bn = blockIdx.x * BN;

    const int aRow = tid >> 1;          // 0..127
    const int aCol = (tid & 1) * 4;     // 0 or 4
    const int bRow = tid >> 5;          // 0..7
    const int bCol = (tid & 31) * 4;    // 0..124

    const int tr = (tid >> 4) * TM;     // thread tile row in block tile
    const int tc = (tid & 15) * TN;

    float acc[TM][TN];
    #pragma unroll
    for (int i = 0; i < TM; i++)
        #pragma unroll
        for (int j = 0; j < TN; j++) acc[i][j] = 0.f;

    for (int k0 = 0; k0 < K; k0 += BK) {
        float4 a4 = *(const float4*)(A + (size_t)(bm + aRow) * K + k0 + aCol);
        As[aCol + 0][aRow] = a4.x;
        As[aCol + 1][aRow] = a4.y;
        As[aCol + 2][aRow] = a4.z;
        As[aCol + 3][aRow] = a4.w;
        *(float4*)(&Bs[bRow][bCol]) =
            *(const float4*)(B + (size_t)(k0 + bRow) * N + bn + bCol);
        __syncthreads();

        #pragma unroll
        for (int kk = 0; kk < BK; kk++) {
            float ra[TM], rb[TN];
            #pragma unroll
            for (int i = 0; i < TM; i++) ra[i] = As[kk][tr + i];
            #pragma unroll
            for (int j = 0; j < TN; j++) rb[j] = Bs[kk][tc + j];
            #pragma unroll
            for (int i = 0; i < TM; i++)
                #pragma unroll
                for (int j = 0; j < TN; j++) acc[i][j] += ra[i] * rb[j];
        }
        __syncthreads();
    }

    #pragma unroll
    for (int i = 0; i < TM; i++) {
        const int m = bm + tr + i;
        #pragma unroll
        for (int j = 0; j < TN; j++) {
            const int n = bn + tc + j;
            float v = acc[i][j] + bias[n];
            if (ep == EP_RES)       v += R[(size_t)m * N + n];
            else if (ep == EP_GELU) v = 0.5f * v * (1.0f + erff(v * 0.70710678118654752f));
            C[(size_t)m * N + n] = v;
        }
    }
}

// ---------------- flash attention (fp32, one query per thread) --------------
#define TQ 128
#define TK 32

__global__ __launch_bounds__(128) void flash_attn(
    const float* __restrict__ Q, const float* __restrict__ Km,
    const float* __restrict__ V, float* __restrict__ O, int causal)
{
    __shared__ float sk[TK][DH];
    __shared__ float sv[TK][DH];
    const int b = blockIdx.z, h = blockIdx.y, qt = blockIdx.x;
    const int t = threadIdx.x;
    const int q = qt * TQ + t;
    const size_t qoff = ((size_t)(b * SEQ + q)) * EMBED + h * DH;

    float4 qv[DH / 4];
    #pragma unroll
    for (int i = 0; i < DH / 4; i++) {
        float4 x = *(const float4*)(Q + qoff + 4 * i);
        x.x *= 0.125f; x.y *= 0.125f; x.z *= 0.125f; x.w *= 0.125f;  // 1/sqrt(64)
        qv[i] = x;
    }
    float4 acc[DH / 4];
    #pragma unroll
    for (int i = 0; i < DH / 4; i++) acc[i] = make_float4(0.f, 0.f, 0.f, 0.f);
    float mi = -1e30f, li = 0.f;

    const int nkt = causal ? (qt + 1) * (TQ / TK) : SEQ / TK;
    for (int kt = 0; kt < nkt; kt++) {
        // cooperative tile load: TK*DH = 2048 floats = 512 float4, 4 per thread
        #pragma unroll
        for (int i = 0; i < 4; i++) {
            int idx = t + i * 128;        // float4 index 0..511
            int r = idx >> 4;             // 16 float4 per row
            int c = (idx & 15) * 4;
            size_t goff = ((size_t)(b * SEQ + kt * TK + r)) * EMBED + h * DH + c;
            *(float4*)(&sk[r][c]) = *(const float4*)(Km + goff);
            *(float4*)(&sv[r][c]) = *(const float4*)(V  + goff);
        }
        __syncthreads();

        float s[TK];
        float tmax = -1e30f;
        #pragma unroll
        for (int j = 0; j < TK; j++) {
            const int k = kt * TK + j;
            float d = -1e30f;
            if (!causal || k <= q) {
                float dd = 0.f;
                #pragma unroll
                for (int i = 0; i < DH / 4; i++) {
                    float4 kv = *(const float4*)(&sk[j][4 * i]);
                    dd += qv[i].x * kv.x + qv[i].y * kv.y + qv[i].z * kv.z + qv[i].w * kv.w;
                }
                d = dd;
            }
            s[j] = d;
            tmax = fmaxf(tmax, d);
        }
        const float mnew = fmaxf(mi, tmax);
        const float corr = __expf(mi - mnew);
        li *= corr;
        #pragma unroll
        for (int i = 0; i < DH / 4; i++) {
            acc[i].x *= corr; acc[i].y *= corr; acc[i].z *= corr; acc[i].w *= corr;
        }
        #pragma unroll
        for (int j = 0; j < TK; j++) {
            const float p = __expf(s[j] - mnew);
            li += p;
            #pragma unroll
            for (int i = 0; i < DH / 4; i++) {
                float4 vv = *(const float4*)(&sv[j][4 * i]);
                acc[i].x += p * vv.x; acc[i].y += p * vv.y;
                acc[i].z += p * vv.z; acc[i].w += p * vv.w;
            }
        }
        mi = mnew;
        __syncthreads();
    }
    const float inv = 1.f / li;
    #pragma unroll
    for (int i = 0; i < DH / 4; i++) {
        float4 o = acc[i];
        o.x *= inv; o.y *= inv; o.z *= inv; o.w *= inv;
        *(float4*)(O + qoff + 4 * i) = o;
    }
}

// ---------------- LayerNorm over last dim (512) -----------------------------
__global__ __launch_bounds__(128) void layernorm_k(
    const float* __restrict__ X, const float* __restrict__ G,
    const float* __restrict__ Bt, float* __restrict__ Y)
{
    const int row = blockIdx.x;
    const int t = threadIdx.x;
    const float* xr = X + (size_t)row * EMBED;
    float4 v = *(const float4*)(xr + t * 4);       // 128 threads * 4 = 512
    float s  = v.x + v.y + v.z + v.w;
    float ss = v.x * v.x + v.y * v.y + v.z * v.z + v.w * v.w;
    #pragma unroll
    for (int o = 16; o > 0; o >>= 1) {
        s  += __shfl_xor_sync(0xffffffffu, s,  o);
        ss += __shfl_xor_sync(0xffffffffu, ss, o);
    }
    __shared__ float sh_s[4], sh_ss[4];
    const int w = t >> 5;
    if ((t & 31) == 0) { sh_s[w] = s; sh_ss[w] = ss; }
    __syncthreads();
    s  = sh_s[0] + sh_s[1] + sh_s[2] + sh_s[3];
    ss = sh_ss[0] + sh_ss[1] + sh_ss[2] + sh_ss[3];
    const float mean = s * (1.f / EMBED);
    const float var  = ss * (1.f / EMBED) - mean * mean;
    const float rstd = rsqrtf(var + 1e-5f);
    float4 gg = *(const float4*)(G  + t * 4);
    float4 bb = *(const float4*)(Bt + t * 4);
    float4 o;
    o.x = (v.x - mean) * rstd * gg.x + bb.x;
    o.y = (v.y - mean) * rstd * gg.y + bb.y;
    o.z = (v.z - mean) * rstd * gg.z + bb.z;
    o.w = (v.w - mean) * rstd * gg.w + bb.w;
    *(float4*)(Y + (size_t)row * EMBED + t * 4) = o;
}

// ---------------- launch --------------------------------------------------
extern "C" void kernel_launch(void* const* d_in, const int* in_sizes, int n_in,
                              void* d_out, int out_size)
{
    const float* x     = (const float*)d_in[0];
    const float* enc   = (const float*)d_in[1];
    const float* sa_wq = (const float*)d_in[2];
    const float* sa_bq = (const float*)d_in[3];
    const float* sa_wk = (const float*)d_in[4];
    const float* sa_bk = (const float*)d_in[5];
    const float* sa_wv = (const float*)d_in[6];
    const float* sa_bv = (const float*)d_in[7];
    const float* sa_wo = (const float*)d_in[8];
    const float* sa_bo = (const float*)d_in[9];
    const float* ca_wq = (const float*)d_in[10];
    const float* ca_bq = (const float*)d_in[11];
    const float* ca_wk = (const float*)d_in[12];
    const float* ca_bk = (const float*)d_in[13];
    const float* ca_wv = (const float*)d_in[14];
    const float* ca_bv = (const float*)d_in[15];
    const float* ca_wo = (const float*)d_in[16];
    const float* ca_bo = (const float*)d_in[17];
    const float* ln1_g = (const float*)d_in[18];
    const float* ln1_b = (const float*)d_in[19];
    const float* ln2_g = (const float*)d_in[20];
    const float* ln2_b = (const float*)d_in[21];
    const float* ln3_g = (const float*)d_in[22];
    const float* ln3_b = (const float*)d_in[23];
    const float* ff_w1 = (const float*)d_in[24];
    const float* ff_b1 = (const float*)d_in[25];
    const float* ff_w2 = (const float*)d_in[26];
    const float* ff_b2 = (const float*)d_in[27];
    float* out = (float*)d_out;

    float *q, *k, *v, *attn, *xb, *hb;
    cudaGetSymbolAddress((void**)&q,    g_q);
    cudaGetSymbolAddress((void**)&k,    g_k);
    cudaGetSymbolAddress((void**)&v,    g_v);
    cudaGetSymbolAddress((void**)&attn, g_attn);
    cudaGetSymbolAddress((void**)&xb,   g_x);
    cudaGetSymbolAddress((void**)&hb,   g_h);

    dim3 g512(EMBED / BN, ROWS / BM);   // (4, 32)
    dim3 gff (FF    / BN, ROWS / BM);   // (16, 32)
    dim3 gfl (SEQ / TQ, NH, BATCH);     // (16, 8, 2)

    // ---- self attention (causal) ----
    sgemm_ep<<<g512, 256>>>(x, sa_wq, sa_bq, nullptr, q, ROWS, EMBED, EMBED, EP_BIAS);
    sgemm_ep<<<g512, 256>>>(x, sa_wk, sa_bk, nullptr, k, ROWS, EMBED, EMBED, EP_BIAS);
    sgemm_ep<<<g512, 256>>>(x, sa_wv, sa_bv, nullptr, v, ROWS, EMBED, EMBED, EP_BIAS);
    flash_attn<<<gfl, 128>>>(q, k, v, attn, 1);
    sgemm_ep<<<g512, 256>>>(attn, sa_wo, sa_bo, x, xb, ROWS, EMBED, EMBED, EP_RES);
    layernorm_k<<<ROWS, 128>>>(xb, ln1_g, ln1_b, xb);

    // ---- cross attention ----
    sgemm_ep<<<g512, 256>>>(xb,  ca_wq, ca_bq, nullptr, q, ROWS, EMBED, EMBED, EP_BIAS);
    sgemm_ep<<<g512, 256>>>(enc, ca_wk, ca_bk, nullptr, k, ROWS, EMBED, EMBED, EP_BIAS);
    sgemm_ep<<<g512, 256>>>(enc, ca_wv, ca_bv, nullptr, v, ROWS, EMBED, EMBED, EP_BIAS);
    flash_attn<<<gfl, 128>>>(q, k, v, attn, 0);
    sgemm_ep<<<g512, 256>>>(attn, ca_wo, ca_bo, xb, xb, ROWS, EMBED, EMBED, EP_RES);
    layernorm_k<<<ROWS, 128>>>(xb, ln2_g, ln2_b, xb);

    // ---- feed-forward ----
    sgemm_ep<<<gff, 256>>>(xb, ff_w1, ff_b1, nullptr, hb, ROWS, FF, EMBED, EP_GELU);
    sgemm_ep<<<g512, 256>>>(hb, ff_w2, ff_b2, xb, xb, ROWS, EMBED, FF, EP_RES);
    layernorm_k<<<ROWS, 128>>>(xb, ln3_g, ln3_b, out);
}